// round 9
// baseline (speedup 1.0000x reference)
#include <cuda_runtime.h>
#include <cuda_bf16.h>

#define L_SEQ 1024
#define NPOS  64
#define NBLOCKS 592   // 4 CTAs/SM * 148 SMs

// ---------------------------------------------------------------------------
// Persistent fused CoPE kernel. 256 threads/block, each block loops over rows
// (stride NBLOCKS). pe lives in REGISTERS (16 floats/thread, loaded once):
//   thread slice: d in [4*dq, 4*dq+4), cols [4*quad, 4*quad+4)
// Per row: GEMV = 16 reg-FMA + shfl fold + 8-way smem reduce; sigmoid gates
// (diag zeroed); clamped suffix-sum scan; lerp gather from Lg.
// Next row's attn/q prefetched at loop top to hide DRAM latency.
// ---------------------------------------------------------------------------
__global__ __launch_bounds__(256, 4) void cope_persist(
    const float* __restrict__ query,      // [rows, 64]
    const float* __restrict__ attn,       // [rows, 1024]
    const float* __restrict__ pe,         // [64, 64] (d, n)
    float* __restrict__ out,              // [rows, 1024]
    int rows)
{
    const int t    = threadIdx.x;
    const int lane = t & 31;
    const int w    = t >> 5;
    const int quad = t & 15;
    const int dq   = t >> 4;              // 0..15

    __shared__ float Lp[8][68];           // folded GEMV partials [warp][col]
    __shared__ float Lg[NPOS + 1];        // Lg[64] = Lg[63]
    __shared__ float wsum[8];

    // pe slice -> registers (once per block lifetime).
    const float4* pe4 = reinterpret_cast<const float4*>(pe);
    float4 per[4];
    #pragma unroll
    for (int j = 0; j < 4; j++) per[j] = __ldg(&pe4[(dq * 4 + j) * 16 + quad]);

    const float4* attn4 = reinterpret_cast<const float4*>(attn);
    const float4* q4    = reinterpret_cast<const float4*>(query);
    float4*       out4  = reinterpret_cast<float4*>(out);
    const int stride = gridDim.x;

    int row = blockIdx.x;
    if (row >= rows) return;
    float4 v  = __ldcs(&attn4[(size_t)row * 256 + t]);
    float4 qv = __ldg(&q4[row * 16 + dq]);

    while (true) {
        // ---- prefetch next row ----
        const int rn = row + stride;
        float4 vn, qn;
        if (rn < rows) {
            vn = __ldcs(&attn4[(size_t)rn * 256 + t]);
            qn = __ldg(&q4[rn * 16 + dq]);
        }

        // ---- GEMV partial: 16 FMA on register pe ----
        float4 a;
        a.x = qv.x * per[0].x; a.y = qv.x * per[0].y;
        a.z = qv.x * per[0].z; a.w = qv.x * per[0].w;
        a.x = fmaf(qv.y, per[1].x, a.x); a.y = fmaf(qv.y, per[1].y, a.y);
        a.z = fmaf(qv.y, per[1].z, a.z); a.w = fmaf(qv.y, per[1].w, a.w);
        a.x = fmaf(qv.z, per[2].x, a.x); a.y = fmaf(qv.z, per[2].y, a.y);
        a.z = fmaf(qv.z, per[2].z, a.z); a.w = fmaf(qv.z, per[2].w, a.w);
        a.x = fmaf(qv.w, per[3].x, a.x); a.y = fmaf(qv.w, per[3].y, a.y);
        a.z = fmaf(qv.w, per[3].z, a.z); a.w = fmaf(qv.w, per[3].w, a.w);
        // fold dq pairs (lane ^ 16 has same quad, adjacent dq)
        a.x += __shfl_xor_sync(0xffffffffu, a.x, 16);
        a.y += __shfl_xor_sync(0xffffffffu, a.y, 16);
        a.z += __shfl_xor_sync(0xffffffffu, a.z, 16);
        a.w += __shfl_xor_sync(0xffffffffu, a.w, 16);
        if (lane < 16)
            *reinterpret_cast<float4*>(&Lp[w][quad * 4]) = a;

        // ---- sigmoid + diagonal zero (elements [4t, 4t+4)) ----
        const int diag = row & (L_SEQ - 1);
        float g0 = __fdividef(1.0f, 1.0f + __expf(-v.x));
        float g1 = __fdividef(1.0f, 1.0f + __expf(-v.y));
        float g2 = __fdividef(1.0f, 1.0f + __expf(-v.z));
        float g3 = __fdividef(1.0f, 1.0f + __expf(-v.w));
        const int c0 = t << 2;
        if (c0     == diag) g0 = 0.0f;
        if (c0 + 1 == diag) g1 = 0.0f;
        if (c0 + 2 == diag) g2 = 0.0f;
        if (c0 + 3 == diag) g3 = 0.0f;
        const float s = g0 + g1 + g2 + g3;

        // ---- warp inclusive scan ----
        float incl = s;
        #pragma unroll
        for (int off = 1; off < 32; off <<= 1) {
            const float nv = __shfl_up_sync(0xffffffffu, incl, off);
            if (lane >= off) incl += nv;
        }
        if (lane == 31) wsum[w] = incl;
        __syncthreads();                 // sync1: Lp + wsum visible

        // ---- Lg column reduce (threads 0..63) ----
        if (t < NPOS) {
            const float sL = ((Lp[0][t] + Lp[1][t]) + (Lp[2][t] + Lp[3][t]))
                           + ((Lp[4][t] + Lp[5][t]) + (Lp[6][t] + Lp[7][t]));
            Lg[t] = sL;
            if (t == NPOS - 1) Lg[NPOS] = sL;
        }

        // ---- block scan combine (overlaps reduce) ----
        float tot = 0.0f, pre = 0.0f;
        #pragma unroll
        for (int k = 0; k < 8; k++) {
            const float wk = wsum[k];
            tot += wk;
            if (k < w) pre += wk;
        }
        const float excl = pre + incl - s;
        __syncthreads();                 // sync2: Lg visible

        // ---- suffix positions + interpolation ----
        const float p0 = tot - excl;
        const float p1 = p0 - g0;
        const float p2 = p1 - g1;
        const float p3 = p2 - g2;

        float4 o;
        if (p3 >= 63.0f) {
            const float Lg63 = Lg[NPOS - 1];
            o.x = Lg63; o.y = Lg63; o.z = Lg63; o.w = Lg63;
        } else {
            float p, pf, ww; int fi;
            p = fminf(fmaxf(p0, 0.0f), 63.0f); pf = floorf(p); ww = p - pf; fi = (int)pf;
            o.x = Lg[fi] + ww * (Lg[fi + 1] - Lg[fi]);
            p = fminf(fmaxf(p1, 0.0f), 63.0f); pf = floorf(p); ww = p - pf; fi = (int)pf;
            o.y = Lg[fi] + ww * (Lg[fi + 1] - Lg[fi]);
            p = fminf(fmaxf(p2, 0.0f), 63.0f); pf = floorf(p); ww = p - pf; fi = (int)pf;
            o.z = Lg[fi] + ww * (Lg[fi + 1] - Lg[fi]);
            p = fminf(fmaxf(p3, 0.0f), 63.0f); pf = floorf(p); ww = p - pf; fi = (int)pf;
            o.w = Lg[fi] + ww * (Lg[fi + 1] - Lg[fi]);
        }

        __stcs(&out4[(size_t)row * 256 + t], o);

        if (rn >= rows) break;
        v = vn; qv = qn; row = rn;
    }
}

extern "C" void kernel_launch(void* const* d_in, const int* in_sizes, int n_in,
                              void* d_out, int out_size) {
    const float* query = (const float*)d_in[0];   // [4,12,1024,64]
    const float* attn  = (const float*)d_in[1];   // [4,12,1024,1024]
    const float* pe    = (const float*)d_in[2];   // [64,64]
    float* out = (float*)d_out;                   // [4,12,1024,1024]

    const int rows = in_sizes[1] / L_SEQ;         // 49152
    cope_persist<<<NBLOCKS, 256>>>(query, attn, pe, out, rows);
}

// round 12
// speedup vs baseline: 1.0652x; 1.0652x over previous
#include <cuda_runtime.h>
#include <cuda_bf16.h>

#define L_SEQ 1024
#define NPOS  64

// ---------------------------------------------------------------------------
// Fused CoPE, 2 rows per block, 256 threads.
// GEMV: thread owns pe tile d in [4dq,4dq+4) x cols [4quad,4quad+4) in regs,
// applied to BOTH rows' q (pe L1 traffic halved vs 1 row/block).
// Per row: sigmoid gates (diag zeroed), clamped suffix-sum scan (dual-row
// shuffle scan), Lg lerp gather. Thread t owns elements [4t,4t+4) of each row.
// ---------------------------------------------------------------------------
__global__ __launch_bounds__(256) void cope2(
    const float* __restrict__ query,      // [rows, 64]
    const float* __restrict__ attn,       // [rows, 1024]
    const float* __restrict__ pe,         // [64, 64] (d, n)
    float* __restrict__ out)              // [rows, 1024]
{
    const int r0   = blockIdx.x * 2;
    const int r1   = r0 + 1;
    const int t    = threadIdx.x;
    const int lane = t & 31;
    const int w    = t >> 5;
    const int quad = t & 15;
    const int dq   = t >> 4;              // 0..15

    __shared__ float LpA[8][64], LpB[8][64];
    __shared__ float LgA[NPOS + 1], LgB[NPOS + 1];
    __shared__ float wsumA[8], wsumB[8];

    // ---- global loads up front ----
    const float4* attn4 = reinterpret_cast<const float4*>(attn);
    const float4* q4    = reinterpret_cast<const float4*>(query);
    const float4* pe4   = reinterpret_cast<const float4*>(pe);

    const float4 vA = __ldcs(&attn4[(size_t)r0 * 256 + t]);
    const float4 vB = __ldcs(&attn4[(size_t)r1 * 256 + t]);
    const float4 qA = __ldg(&q4[r0 * 16 + dq]);
    const float4 qB = __ldg(&q4[r1 * 16 + dq]);
    float4 per[4];
    #pragma unroll
    for (int j = 0; j < 4; j++) per[j] = __ldg(&pe4[(dq * 4 + j) * 16 + quad]);

    // ---- GEMV partials for both rows (register pe tile) ----
    {
        float4 a, b;
        a.x = qA.x * per[0].x; a.y = qA.x * per[0].y;
        a.z = qA.x * per[0].z; a.w = qA.x * per[0].w;
        b.x = qB.x * per[0].x; b.y = qB.x * per[0].y;
        b.z = qB.x * per[0].z; b.w = qB.x * per[0].w;
        a.x = fmaf(qA.y, per[1].x, a.x); a.y = fmaf(qA.y, per[1].y, a.y);
        a.z = fmaf(qA.y, per[1].z, a.z); a.w = fmaf(qA.y, per[1].w, a.w);
        b.x = fmaf(qB.y, per[1].x, b.x); b.y = fmaf(qB.y, per[1].y, b.y);
        b.z = fmaf(qB.y, per[1].z, b.z); b.w = fmaf(qB.y, per[1].w, b.w);
        a.x = fmaf(qA.z, per[2].x, a.x); a.y = fmaf(qA.z, per[2].y, a.y);
        a.z = fmaf(qA.z, per[2].z, a.z); a.w = fmaf(qA.z, per[2].w, a.w);
        b.x = fmaf(qB.z, per[2].x, b.x); b.y = fmaf(qB.z, per[2].y, b.y);
        b.z = fmaf(qB.z, per[2].z, b.z); b.w = fmaf(qB.z, per[2].w, b.w);
        a.x = fmaf(qA.w, per[3].x, a.x); a.y = fmaf(qA.w, per[3].y, a.y);
        a.z = fmaf(qA.w, per[3].z, a.z); a.w = fmaf(qA.w, per[3].w, a.w);
        b.x = fmaf(qB.w, per[3].x, b.x); b.y = fmaf(qB.w, per[3].y, b.y);
        b.z = fmaf(qB.w, per[3].z, b.z); b.w = fmaf(qB.w, per[3].w, b.w);
        // fold dq pairs (lane^16: same quad, adjacent dq)
        a.x += __shfl_xor_sync(0xffffffffu, a.x, 16);
        a.y += __shfl_xor_sync(0xffffffffu, a.y, 16);
        a.z += __shfl_xor_sync(0xffffffffu, a.z, 16);
        a.w += __shfl_xor_sync(0xffffffffu, a.w, 16);
        b.x += __shfl_xor_sync(0xffffffffu, b.x, 16);
        b.y += __shfl_xor_sync(0xffffffffu, b.y, 16);
        b.z += __shfl_xor_sync(0xffffffffu, b.z, 16);
        b.w += __shfl_xor_sync(0xffffffffu, b.w, 16);
        if (lane < 16) {
            *reinterpret_cast<float4*>(&LpA[w][quad * 4]) = a;
            *reinterpret_cast<float4*>(&LpB[w][quad * 4]) = b;
        }
    }

    // ---- sigmoid + diagonal zero (elements [4t,4t+4) of each row) ----
    const int diagA = r0 & (L_SEQ - 1);
    const int diagB = r1 & (L_SEQ - 1);
    float gA[4], gB[4];
    gA[0] = __fdividef(1.0f, 1.0f + __expf(-vA.x));
    gA[1] = __fdividef(1.0f, 1.0f + __expf(-vA.y));
    gA[2] = __fdividef(1.0f, 1.0f + __expf(-vA.z));
    gA[3] = __fdividef(1.0f, 1.0f + __expf(-vA.w));
    gB[0] = __fdividef(1.0f, 1.0f + __expf(-vB.x));
    gB[1] = __fdividef(1.0f, 1.0f + __expf(-vB.y));
    gB[2] = __fdividef(1.0f, 1.0f + __expf(-vB.z));
    gB[3] = __fdividef(1.0f, 1.0f + __expf(-vB.w));
    const int c0 = t << 2;
    #pragma unroll
    for (int i = 0; i < 4; i++) {
        if (c0 + i == diagA) gA[i] = 0.0f;
        if (c0 + i == diagB) gB[i] = 0.0f;
    }
    const float sA = gA[0] + gA[1] + gA[2] + gA[3];
    const float sB = gB[0] + gB[1] + gB[2] + gB[3];

    // ---- dual warp inclusive scan ----
    float iA = sA, iB = sB;
    #pragma unroll
    for (int off = 1; off < 32; off <<= 1) {
        const float nA = __shfl_up_sync(0xffffffffu, iA, off);
        const float nB = __shfl_up_sync(0xffffffffu, iB, off);
        if (lane >= off) { iA += nA; iB += nB; }
    }
    if (lane == 31) { wsumA[w] = iA; wsumB[w] = iB; }
    __syncthreads();   // Lp + wsum visible

    // ---- Lg reduces in parallel: warps 0-1 -> row A, warps 2-3 -> row B ----
    if (t < NPOS) {
        const float s = ((LpA[0][t] + LpA[1][t]) + (LpA[2][t] + LpA[3][t]))
                      + ((LpA[4][t] + LpA[5][t]) + (LpA[6][t] + LpA[7][t]));
        LgA[t] = s;
        if (t == NPOS - 1) LgA[NPOS] = s;
    } else if (t < 2 * NPOS) {
        const int n = t - NPOS;
        const float s = ((LpB[0][n] + LpB[1][n]) + (LpB[2][n] + LpB[3][n]))
                      + ((LpB[4][n] + LpB[5][n]) + (LpB[6][n] + LpB[7][n]));
        LgB[n] = s;
        if (n == NPOS - 1) LgB[NPOS] = s;
    }

    // ---- block scan combine (overlaps reduce) ----
    float totA = 0.0f, totB = 0.0f, preA = 0.0f, preB = 0.0f;
    #pragma unroll
    for (int k = 0; k < 8; k++) {
        const float a = wsumA[k], b = wsumB[k];
        totA += a; totB += b;
        if (k < w) { preA += a; preB += b; }
    }
    const float exclA = preA + iA - sA;
    const float exclB = preB + iB - sB;
    __syncthreads();   // Lg visible

    // ---- row A: suffix positions + interpolation ----
    float4 oA, oB;
    {
        const float p0 = totA - exclA;
        const float p1 = p0 - gA[0];
        const float p2 = p1 - gA[1];
        const float p3 = p2 - gA[2];
        if (p3 >= 63.0f) {
            const float L63 = LgA[NPOS - 1];
            oA.x = L63; oA.y = L63; oA.z = L63; oA.w = L63;
        } else {
            float p, pf, ww; int fi;
            p = fminf(fmaxf(p0, 0.0f), 63.0f); pf = floorf(p); ww = p - pf; fi = (int)pf;
            oA.x = LgA[fi] + ww * (LgA[fi + 1] - LgA[fi]);
            p = fminf(fmaxf(p1, 0.0f), 63.0f); pf = floorf(p); ww = p - pf; fi = (int)pf;
            oA.y = LgA[fi] + ww * (LgA[fi + 1] - LgA[fi]);
            p = fminf(fmaxf(p2, 0.0f), 63.0f); pf = floorf(p); ww = p - pf; fi = (int)pf;
            oA.z = LgA[fi] + ww * (LgA[fi + 1] - LgA[fi]);
            p = fminf(fmaxf(p3, 0.0f), 63.0f); pf = floorf(p); ww = p - pf; fi = (int)pf;
            oA.w = LgA[fi] + ww * (LgA[fi + 1] - LgA[fi]);
        }
    }
    // ---- row B ----
    {
        const float p0 = totB - exclB;
        const float p1 = p0 - gB[0];
        const float p2 = p1 - gB[1];
        const float p3 = p2 - gB[2];
        if (p3 >= 63.0f) {
            const float L63 = LgB[NPOS - 1];
            oB.x = L63; oB.y = L63; oB.z = L63; oB.w = L63;
        } else {
            float p, pf, ww; int fi;
            p = fminf(fmaxf(p0, 0.0f), 63.0f); pf = floorf(p); ww = p - pf; fi = (int)pf;
            oB.x = LgB[fi] + ww * (LgB[fi + 1] - LgB[fi]);
            p = fminf(fmaxf(p1, 0.0f), 63.0f); pf = floorf(p); ww = p - pf; fi = (int)pf;
            oB.y = LgB[fi] + ww * (LgB[fi + 1] - LgB[fi]);
            p = fminf(fmaxf(p2, 0.0f), 63.0f); pf = floorf(p); ww = p - pf; fi = (int)pf;
            oB.z = LgB[fi] + ww * (LgB[fi + 1] - LgB[fi]);
            p = fminf(fmaxf(p3, 0.0f), 63.0f); pf = floorf(p); ww = p - pf; fi = (int)pf;
            oB.w = LgB[fi] + ww * (LgB[fi + 1] - LgB[fi]);
        }
    }

    float4* out4 = reinterpret_cast<float4*>(out);
    __stcs(&out4[(size_t)r0 * 256 + t], oA);
    __stcs(&out4[(size_t)r1 * 256 + t], oB);
}

extern "C" void kernel_launch(void* const* d_in, const int* in_sizes, int n_in,
                              void* d_out, int out_size) {
    const float* query = (const float*)d_in[0];   // [4,12,1024,64]
    const float* attn  = (const float*)d_in[1];   // [4,12,1024,1024]
    const float* pe    = (const float*)d_in[2];   // [64,64]
    float* out = (float*)d_out;                   // [4,12,1024,1024]

    const int rows = in_sizes[1] / L_SEQ;         // 49152
    cope2<<<rows / 2, 256>>>(query, attn, pe, out);
}

// round 14
// speedup vs baseline: 1.0885x; 1.0218x over previous
#include <cuda_runtime.h>
#include <cuda_bf16.h>

#define L_SEQ 1024
#define NPOS  64

// ---------------------------------------------------------------------------
// Fused CoPE, 2 rows per block, 256 threads, threads SPLIT by row:
//   - GEMV shared: each thread holds a 4x4 pe register tile (d in
//     [4dq,4dq+4) x cols [4quad,4quad+4)) applied to BOTH rows' q
//     (pe L1 traffic halved vs 1 row/block).
//   - Everything else per-half: threads 0-127 own row A, 128-255 own row B.
//     Each half-thread owns chunks [4tl,4tl+4) AND [512+4tl,512+4tl+4) of
//     its row (full 1024-element coverage), dual-chunk scan as in R8.
// ---------------------------------------------------------------------------
__global__ __launch_bounds__(256) void cope2s(
    const float* __restrict__ query,      // [rows, 64]
    const float* __restrict__ attn,       // [rows, 1024]
    const float* __restrict__ pe,         // [64, 64] (d, n)
    float* __restrict__ out)              // [rows, 1024]
{
    const int r0   = blockIdx.x * 2;
    const int t    = threadIdx.x;
    const int lane = t & 31;
    const int w    = t >> 5;              // 0..7
    const int half = t >> 7;              // 0 = row A, 1 = row B
    const int tl   = t & 127;             // index within half
    const int wh   = w & 3;               // warp within half
    const int quad = t & 15;
    const int dq   = t >> 4;              // 0..15

    __shared__ float LpA[8][64], LpB[8][64];
    __shared__ float LgA[NPOS + 1], LgB[NPOS + 1];
    __shared__ float wsumA[8], wsumB[8];

    const float4* attn4 = reinterpret_cast<const float4*>(attn);
    const float4* q4    = reinterpret_cast<const float4*>(query);
    const float4* pe4   = reinterpret_cast<const float4*>(pe);

    const int myrow = r0 + half;
    // ---- own row's two attn chunks (the DRAM long poles) ----
    const float4 va = __ldcs(&attn4[(size_t)myrow * 256 + tl]);
    const float4 vb = __ldcs(&attn4[(size_t)myrow * 256 + 128 + tl]);
    // ---- q slices for both rows + pe tile ----
    const float4 qA = __ldg(&q4[r0 * 16 + dq]);
    const float4 qB = __ldg(&q4[(r0 + 1) * 16 + dq]);
    float4 per[4];
    #pragma unroll
    for (int j = 0; j < 4; j++) per[j] = __ldg(&pe4[(dq * 4 + j) * 16 + quad]);

    // ---- shared GEMV: apply pe tile to both rows (pure ILP) ----
    {
        float4 a, b;
        a.x = qA.x * per[0].x; a.y = qA.x * per[0].y;
        a.z = qA.x * per[0].z; a.w = qA.x * per[0].w;
        b.x = qB.x * per[0].x; b.y = qB.x * per[0].y;
        b.z = qB.x * per[0].z; b.w = qB.x * per[0].w;
        a.x = fmaf(qA.y, per[1].x, a.x); a.y = fmaf(qA.y, per[1].y, a.y);
        a.z = fmaf(qA.y, per[1].z, a.z); a.w = fmaf(qA.y, per[1].w, a.w);
        b.x = fmaf(qB.y, per[1].x, b.x); b.y = fmaf(qB.y, per[1].y, b.y);
        b.z = fmaf(qB.y, per[1].z, b.z); b.w = fmaf(qB.y, per[1].w, b.w);
        a.x = fmaf(qA.z, per[2].x, a.x); a.y = fmaf(qA.z, per[2].y, a.y);
        a.z = fmaf(qA.z, per[2].z, a.z); a.w = fmaf(qA.z, per[2].w, a.w);
        b.x = fmaf(qB.z, per[2].x, b.x); b.y = fmaf(qB.z, per[2].y, b.y);
        b.z = fmaf(qB.z, per[2].z, b.z); b.w = fmaf(qB.z, per[2].w, b.w);
        a.x = fmaf(qA.w, per[3].x, a.x); a.y = fmaf(qA.w, per[3].y, a.y);
        a.z = fmaf(qA.w, per[3].z, a.z); a.w = fmaf(qA.w, per[3].w, a.w);
        b.x = fmaf(qB.w, per[3].x, b.x); b.y = fmaf(qB.w, per[3].y, b.y);
        b.z = fmaf(qB.w, per[3].z, b.z); b.w = fmaf(qB.w, per[3].w, b.w);
        // fold dq pairs (lane^16: same quad, adjacent dq) -> d range [8w,8w+8)
        a.x += __shfl_xor_sync(0xffffffffu, a.x, 16);
        a.y += __shfl_xor_sync(0xffffffffu, a.y, 16);
        a.z += __shfl_xor_sync(0xffffffffu, a.z, 16);
        a.w += __shfl_xor_sync(0xffffffffu, a.w, 16);
        b.x += __shfl_xor_sync(0xffffffffu, b.x, 16);
        b.y += __shfl_xor_sync(0xffffffffu, b.y, 16);
        b.z += __shfl_xor_sync(0xffffffffu, b.z, 16);
        b.w += __shfl_xor_sync(0xffffffffu, b.w, 16);
        if (lane < 16) {
            *reinterpret_cast<float4*>(&LpA[w][quad * 4]) = a;
            *reinterpret_cast<float4*>(&LpB[w][quad * 4]) = b;
        }
    }

    // ---- own row: sigmoid + diagonal zero, both chunks ----
    const int diag = myrow & (L_SEQ - 1);
    float g[8];
    g[0] = __fdividef(1.0f, 1.0f + __expf(-va.x));
    g[1] = __fdividef(1.0f, 1.0f + __expf(-va.y));
    g[2] = __fdividef(1.0f, 1.0f + __expf(-va.z));
    g[3] = __fdividef(1.0f, 1.0f + __expf(-va.w));
    g[4] = __fdividef(1.0f, 1.0f + __expf(-vb.x));
    g[5] = __fdividef(1.0f, 1.0f + __expf(-vb.y));
    g[6] = __fdividef(1.0f, 1.0f + __expf(-vb.z));
    g[7] = __fdividef(1.0f, 1.0f + __expf(-vb.w));
    const int cA = tl << 2;
    const int cB = 512 + (tl << 2);
    #pragma unroll
    for (int i = 0; i < 4; i++) if (cA + i == diag) g[i] = 0.0f;
    #pragma unroll
    for (int i = 0; i < 4; i++) if (cB + i == diag) g[4 + i] = 0.0f;

    const float sA = g[0] + g[1] + g[2] + g[3];
    const float sB = g[4] + g[5] + g[6] + g[7];

    // ---- dual warp inclusive scan (own row's two chunks) ----
    float iA = sA, iB = sB;
    #pragma unroll
    for (int off = 1; off < 32; off <<= 1) {
        const float nA = __shfl_up_sync(0xffffffffu, iA, off);
        const float nB = __shfl_up_sync(0xffffffffu, iB, off);
        if (lane >= off) { iA += nA; iB += nB; }
    }
    if (lane == 31) { wsumA[w] = iA; wsumB[w] = iB; }
    __syncthreads();   // Lp + wsum visible

    // ---- Lg reduces in parallel: t<64 -> row A, 64<=t<128 -> row B ----
    if (t < NPOS) {
        const float sL = ((LpA[0][t] + LpA[1][t]) + (LpA[2][t] + LpA[3][t]))
                       + ((LpA[4][t] + LpA[5][t]) + (LpA[6][t] + LpA[7][t]));
        LgA[t] = sL;
        if (t == NPOS - 1) LgA[NPOS] = sL;
    } else if (t < 2 * NPOS) {
        const int n = t - NPOS;
        const float sL = ((LpB[0][n] + LpB[1][n]) + (LpB[2][n] + LpB[3][n]))
                       + ((LpB[4][n] + LpB[5][n]) + (LpB[6][n] + LpB[7][n]));
        LgB[n] = sL;
        if (n == NPOS - 1) LgB[NPOS] = sL;
    }

    // ---- block scan combine over own half's 4 warps ----
    const int base = half * 4;
    float totA = 0.0f, totB = 0.0f, preA = 0.0f, preB = 0.0f;
    #pragma unroll
    for (int k = 0; k < 4; k++) {
        const float a = wsumA[base + k], b = wsumB[base + k];
        totA += a; totB += b;
        if (k < wh) { preA += a; preB += b; }
    }
    const float total = totA + totB;
    const float exclA = preA + iA - sA;          // exclusive prefix at cA
    const float exclB = totA + preB + iB - sB;   // exclusive prefix at cB
    __syncthreads();   // Lg visible

    const float* __restrict__ Lg = half ? LgB : LgA;
    const float Lg63 = Lg[NPOS - 1];
    float4 oA, oB;

    // ---- chunk A: suffix positions + interpolation ----
    {
        const float p0 = total - exclA;
        const float p1 = p0 - g[0];
        const float p2 = p1 - g[1];
        const float p3 = p2 - g[2];
        if (p3 >= 63.0f) {
            oA.x = Lg63; oA.y = Lg63; oA.z = Lg63; oA.w = Lg63;
        } else {
            float p, pf, ww; int fi;
            p = fminf(fmaxf(p0, 0.0f), 63.0f); pf = floorf(p); ww = p - pf; fi = (int)pf;
            oA.x = Lg[fi] + ww * (Lg[fi + 1] - Lg[fi]);
            p = fminf(fmaxf(p1, 0.0f), 63.0f); pf = floorf(p); ww = p - pf; fi = (int)pf;
            oA.y = Lg[fi] + ww * (Lg[fi + 1] - Lg[fi]);
            p = fminf(fmaxf(p2, 0.0f), 63.0f); pf = floorf(p); ww = p - pf; fi = (int)pf;
            oA.z = Lg[fi] + ww * (Lg[fi + 1] - Lg[fi]);
            p = fminf(fmaxf(p3, 0.0f), 63.0f); pf = floorf(p); ww = p - pf; fi = (int)pf;
            oA.w = Lg[fi] + ww * (Lg[fi + 1] - Lg[fi]);
        }
    }
    // ---- chunk B ----
    {
        const float p0 = total - exclB;
        const float p1 = p0 - g[4];
        const float p2 = p1 - g[5];
        const float p3 = p2 - g[6];
        if (p3 >= 63.0f) {
            oB.x = Lg63; oB.y = Lg63; oB.z = Lg63; oB.w = Lg63;
        } else {
            float p, pf, ww; int fi;
            p = fminf(fmaxf(p0, 0.0f), 63.0f); pf = floorf(p); ww = p - pf; fi = (int)pf;
            oB.x = Lg[fi] + ww * (Lg[fi + 1] - Lg[fi]);
            p = fminf(fmaxf(p1, 0.0f), 63.0f); pf = floorf(p); ww = p - pf; fi = (int)pf;
            oB.y = Lg[fi] + ww * (Lg[fi + 1] - Lg[fi]);
            p = fminf(fmaxf(p2, 0.0f), 63.0f); pf = floorf(p); ww = p - pf; fi = (int)pf;
            oB.z = Lg[fi] + ww * (Lg[fi + 1] - Lg[fi]);
            p = fminf(fmaxf(p3, 0.0f), 63.0f); pf = floorf(p); ww = p - pf; fi = (int)pf;
            oB.w = Lg[fi] + ww * (Lg[fi + 1] - Lg[fi]);
        }
    }

    float4* out4 = reinterpret_cast<float4*>(out);
    __stcs(&out4[(size_t)myrow * 256 + tl],       oA);
    __stcs(&out4[(size_t)myrow * 256 + 128 + tl], oB);
}

extern "C" void kernel_launch(void* const* d_in, const int* in_sizes, int n_in,
                              void* d_out, int out_size) {
    const float* query = (const float*)d_in[0];   // [4,12,1024,64]
    const float* attn  = (const float*)d_in[1];   // [4,12,1024,1024]
    const float* pe    = (const float*)d_in[2];   // [64,64]
    float* out = (float*)d_out;                   // [4,12,1024,1024]

    const int rows = in_sizes[1] / L_SEQ;         // 49152
    cope2s<<<rows / 2, 256>>>(query, attn, pe, out);
}